// round 16
// baseline (speedup 1.0000x reference)
#include <cuda_runtime.h>
#include <cuda_fp16.h>
#include <math.h>
#include <stdint.h>

#define BB   32
#define SS   512
#define DD   768
#define HH   384
#define G3   (3*HH)      // 1152
#define NROWS (2*G3)     // 2304
#define M16K (SS*BB)     // 16384
#define KCP  (2*DD)      // 1536  (2-term split-concat K)

// ---------------- scratch (static device globals; no runtime alloc) ----------
__device__ float g_XW[(size_t)NROWS * M16K];        // [n][m], m = t*32+b
__device__ float g_OUT[(size_t)M16K * (2*HH)];      // [m][768]
__device__ float g_H[2][2][2][HH * 16];             // [dir][bg][buf][k*16+bl]
__device__ int   g_bar[2 * 2 * SS];                 // per-(dir,bg,step) counters
__device__ float g_scores[M16K];
// fp16 split-concat operands
__device__ __half g_Ac [(size_t)NROWS * KCP];       // proj A: [Wh|Wl]
__device__ __half g_Bc [(size_t)M16K  * KCP];       // proj B: [Xh|Xh]
__device__ __half g_Wac[(size_t)(2*HH) * KCP];      // attn A: [Wah|Wal]
__device__ __half g_Oc [(size_t)M16K  * KCP];       // attn B: [Oh|Oh]

// ============================ PTX helpers ====================================
__device__ __forceinline__ uint32_t smem_u32(const void* p) {
    uint32_t a;
    asm("{ .reg .u64 t; cvta.to.shared.u64 t, %1; cvt.u32.u64 %0, t; }"
        : "=r"(a) : "l"(p));
    return a;
}

#define CP_ASYNC16(saddr, gptr) \
    asm volatile("cp.async.cg.shared.global [%0], [%1], 16;" \
                 :: "r"(saddr), "l"(gptr) : "memory")
#define CP_COMMIT() asm volatile("cp.async.commit_group;" ::: "memory")
#define CP_WAIT2()  asm volatile("cp.async.wait_group 2;" ::: "memory")

#define LDMATRIX_X4(r0, r1, r2, r3, addr) \
    asm volatile("ldmatrix.sync.aligned.m8n8.x4.shared.b16 {%0,%1,%2,%3}, [%4];" \
                 : "=r"(r0), "=r"(r1), "=r"(r2), "=r"(r3) : "r"(addr))

#define MMA16816(c0, c1, c2, c3, a0, a1, a2, a3, b0, b1) \
    asm volatile("mma.sync.aligned.m16n8k16.row.col.f32.f16.f16.f32 " \
                 "{%0,%1,%2,%3}, {%4,%5,%6,%7}, {%8,%9}, {%0,%1,%2,%3};" \
                 : "+f"(c0), "+f"(c1), "+f"(c2), "+f"(c3) \
                 : "r"(a0), "r"(a1), "r"(a2), "r"(a3), "r"(b0), "r"(b1))

__device__ __forceinline__ void red_release_add(int* p) {
    asm volatile("red.release.gpu.global.add.u32 [%0], 1;" :: "l"(p) : "memory");
}
__device__ __forceinline__ int ld_acquire(const int* p) {
    int v;
    asm volatile("ld.acquire.gpu.global.u32 %0, [%1];" : "=r"(v) : "l"(p) : "memory");
    return v;
}

// packed fp32x2
__device__ __forceinline__ unsigned long long pk2(float a, float b) {
    unsigned long long r;
    asm("mov.b64 %0, {%1, %2};" : "=l"(r) : "f"(a), "f"(b));
    return r;
}
__device__ __forceinline__ float2 upk2(unsigned long long v) {
    float2 f;
    asm("mov.b64 {%0, %1}, %2;" : "=f"(f.x), "=f"(f.y) : "l"(v));
    return f;
}
#define FMA2(d, a, b, c) \
    asm("fma.rn.f32x2 %0, %1, %2, %3;" : "=l"(d) : "l"(a), "l"(b), "l"(c))

// ---------------------------------- init ------------------------------------
__global__ void init_kernel() {
    int idx = blockIdx.x * blockDim.x + threadIdx.x;
    int nthr = gridDim.x * blockDim.x;
    float* h = &g_H[0][0][0][0];
    for (int i = idx; i < 2 * 2 * 2 * HH * 16; i += nthr) h[i] = 0.f;
    for (int i = idx; i < 2 * 2 * SS; i += nthr) g_bar[i] = 0;
    for (int i = idx; i < M16K; i += nthr) g_scores[i] = 0.f;
}

// ---------------- fp32 -> fp16 hi/lo split + K-concat conversion -------------
__global__ void __launch_bounds__(256) convert_split(
    const float* __restrict__ ip,
    const float* __restrict__ Wf, const float* __restrict__ Wb,
    const float* __restrict__ Wa)
{
    const int TOT = (M16K + NROWS + 2 * HH) * (DD / 4);
    int idx = blockIdx.x * blockDim.x + threadIdx.x;
    if (idx >= TOT) return;
    int row = idx / (DD / 4);
    int k = (idx - row * (DD / 4)) * 4;

    const float* src;
    if (row < M16K) {
        int b = row & 31, t = row >> 5;
        src = ip + ((size_t)(b * SS + t)) * DD + k;
    } else if (row < M16K + NROWS) {
        int n = row - M16K;
        src = ((n < G3) ? (Wf + (size_t)n * DD) : (Wb + (size_t)(n - G3) * DD)) + k;
    } else {
        int n = row - M16K - NROWS;
        src = Wa + (size_t)n * (2 * HH) + k;
    }
    float4 v = *(const float4*)src;
    union { __half h[4]; uint2 u; } hi, lo;
    hi.h[0] = __float2half_rn(v.x); lo.h[0] = __float2half_rn(v.x - __half2float(hi.h[0]));
    hi.h[1] = __float2half_rn(v.y); lo.h[1] = __float2half_rn(v.y - __half2float(hi.h[1]));
    hi.h[2] = __float2half_rn(v.z); lo.h[2] = __float2half_rn(v.z - __half2float(hi.h[2]));
    hi.h[3] = __float2half_rn(v.w); lo.h[3] = __float2half_rn(v.w - __half2float(hi.h[3]));

    if (row < M16K) {                        // X: [h | h]
        __half* dst = g_Bc + (size_t)row * KCP;
        *(uint2*)(dst + k)      = hi.u;
        *(uint2*)(dst + DD + k) = hi.u;
    } else if (row < M16K + NROWS) {         // Wcat: [h | l]
        __half* dst = g_Ac + (size_t)(row - M16K) * KCP;
        *(uint2*)(dst + k)      = hi.u;
        *(uint2*)(dst + DD + k) = lo.u;
    } else {                                 // Wa: [h | l]
        __half* dst = g_Wac + (size_t)(row - M16K - NROWS) * KCP;
        *(uint2*)(dst + k)      = hi.u;
        *(uint2*)(dst + DD + k) = lo.u;
    }
}

// -------------------- OUT fp32 -> fp16 [h|h] (for attn HGEMM) ---------------
__global__ void __launch_bounds__(256) out_convert() {
    int idx = blockIdx.x * blockDim.x + threadIdx.x;
    if (idx >= M16K * (DD / 4)) return;
    int m = idx / (DD / 4);
    int k = (idx - m * (DD / 4)) * 4;
    float4 v = *(const float4*)&g_OUT[(size_t)m * (2 * HH) + k];
    union { __half h[4]; uint2 u; } hi;
    hi.h[0] = __float2half_rn(v.x);
    hi.h[1] = __float2half_rn(v.y);
    hi.h[2] = __float2half_rn(v.z);
    hi.h[3] = __float2half_rn(v.w);
    __half* dst = g_Oc + (size_t)m * KCP;
    *(uint2*)(dst + k)      = hi.u;   // [h | h]
    *(uint2*)(dst + DD + k) = hi.u;
}

// ----------------------- shared HGEMM (mma.sync) -----------------------------
// C[n 256][m 128] = A[n][K=1536] * B[m][K]^T. 8 warps = 4(n) x 2(m).
#define HG_A_ST 20480                   // 256 rows * 80B
#define HG_B_ST 10240                   // 128 rows * 80B
#define HG_DYN_SMEM (4 * (HG_A_ST + HG_B_ST))   // 122880

template <int MODE>
__global__ void __launch_bounds__(256, 1) hgemm_kernel(
    const __half* __restrict__ Ag, const __half* __restrict__ Bg,
    const float* __restrict__ e0, const float* __restrict__ e1)
{
    extern __shared__ char dyn[];
    const uint32_t Abase = smem_u32(dyn);
    const uint32_t Bbase = Abase + 4 * HG_A_ST;

    const int tid  = threadIdx.x;
    const int wid  = tid >> 5, lane = tid & 31;
    const int wn   = wid >> 1;
    const int wm   = wid & 1;
    const int n0   = blockIdx.x * 256;
    const int m0   = blockIdx.y * 128;

    const int KT = KCP / 32;              // 48

    auto load_stage = [&](int buf, int kt) {
        uint32_t as = Abase + buf * HG_A_ST;
        uint32_t bs = Bbase + buf * HG_B_ST;
#pragma unroll
        for (int i = 0; i < 4; ++i) {
            int idx = tid + i * 256;
            int row = idx >> 2, c = idx & 3;
            const __half* ga = Ag + (size_t)(n0 + row) * KCP + kt * 32 + c * 8;
            CP_ASYNC16(as + row * 80 + c * 16, ga);
        }
#pragma unroll
        for (int i = 0; i < 2; ++i) {
            int idx = tid + i * 256;
            int row = idx >> 2, c = idx & 3;
            const __half* gb = Bg + (size_t)(m0 + row) * KCP + kt * 32 + c * 8;
            CP_ASYNC16(bs + row * 80 + c * 16, gb);
        }
        CP_COMMIT();
    };

    float acc[4][8][4];
#pragma unroll
    for (int i = 0; i < 4; i++)
#pragma unroll
        for (int j = 0; j < 8; j++)
#pragma unroll
            for (int r = 0; r < 4; r++) acc[i][j][r] = 0.f;

    load_stage(0, 0);
    load_stage(1, 1);
    load_stage(2, 2);

    const int lr = lane & 15;
    const int lc = lane >> 4;

    for (int kt = 0; kt < KT; ++kt) {
        CP_WAIT2();
        __syncthreads();
        if (kt + 3 < KT) load_stage((kt + 3) & 3, kt + 3);
        else CP_COMMIT();

        uint32_t as = Abase + (kt & 3) * HG_A_ST;
        uint32_t bs = Bbase + (kt & 3) * HG_B_ST;

#pragma unroll
        for (int kk = 0; kk < 2; ++kk) {
            uint32_t bfr[8][2];
#pragma unroll
            for (int bm = 0; bm < 4; ++bm) {
                uint32_t r0, r1, r2, r3;
                uint32_t addr = bs + (wm * 64 + bm * 16 + lr) * 80 + (kk * 2 + lc) * 16;
                LDMATRIX_X4(r0, r1, r2, r3, addr);
                bfr[bm * 2 + 0][0] = r0; bfr[bm * 2 + 0][1] = r2;
                bfr[bm * 2 + 1][0] = r1; bfr[bm * 2 + 1][1] = r3;
            }
#pragma unroll
            for (int fn = 0; fn < 4; ++fn) {
                uint32_t a0, a1, a2, a3;
                uint32_t addr = as + (wn * 64 + fn * 16 + lr) * 80 + (kk * 2 + lc) * 16;
                LDMATRIX_X4(a0, a1, a2, a3, addr);
#pragma unroll
                for (int fm = 0; fm < 8; ++fm) {
                    MMA16816(acc[fn][fm][0], acc[fn][fm][1], acc[fn][fm][2], acc[fn][fm][3],
                             a0, a1, a2, a3, bfr[fm][0], bfr[fm][1]);
                }
            }
        }
    }

    const int crow = lane >> 2;
    const int ccol = 2 * (lane & 3);

    if (MODE == 0) {
#pragma unroll
        for (int fn = 0; fn < 4; ++fn) {
#pragma unroll
            for (int fm = 0; fm < 8; ++fm) {
                int n = n0 + wn * 64 + fn * 16 + crow;
                int n2 = n + 8;
                int c = m0 + wm * 64 + fm * 8 + ccol;
                float bv1 = (n  < G3) ? __ldg(e0 + n)  : __ldg(e1 + n  - G3);
                float bv2 = (n2 < G3) ? __ldg(e0 + n2) : __ldg(e1 + n2 - G3);
                float2 v1 = make_float2(acc[fn][fm][0] + bv1, acc[fn][fm][1] + bv1);
                float2 v2 = make_float2(acc[fn][fm][2] + bv2, acc[fn][fm][3] + bv2);
                *(float2*)&g_XW[(size_t)n  * M16K + c] = v1;
                *(float2*)&g_XW[(size_t)n2 * M16K + c] = v2;
            }
        }
    } else {
        __syncthreads();
        float* Msum = (float*)dyn;          // [128]
        if (tid < 128) Msum[tid] = 0.f;
        __syncthreads();
#pragma unroll
        for (int fm = 0; fm < 8; ++fm) {
            int c = wm * 64 + fm * 8 + ccol;
            float s0 = 0.f, s1 = 0.f;
#pragma unroll
            for (int fn = 0; fn < 4; ++fn) {
                int na = n0 + wn * 64 + fn * 16 + crow;
                int nb = na + 8;
                float ba_a = __ldg(e0 + na), ba_b = __ldg(e0 + nb);
                float cx_a = __ldg(e1 + na), cx_b = __ldg(e1 + nb);
                s0 += tanhf(acc[fn][fm][0] + ba_a) * cx_a
                    + tanhf(acc[fn][fm][2] + ba_b) * cx_b;
                s1 += tanhf(acc[fn][fm][1] + ba_a) * cx_a
                    + tanhf(acc[fn][fm][3] + ba_b) * cx_b;
            }
            atomicAdd(&Msum[c], s0);
            atomicAdd(&Msum[c + 1], s1);
        }
        __syncthreads();
        if (tid < 128) atomicAdd(&g_scores[m0 + tid], Msum[tid]);
    }
}

// ------------------- GRU recurrence (FFMA2, 2-way batch split) ---------------
// 128 CTAs = 2 dir x 2 batch-groups x 32. CTA: 12 units x 16 batches.
// 384 threads = 12 warps = 3 ug x 4 kq; lane: uu = lane>>3 (4 units/warp),
// p = lane&7 (8 batch-pairs). Barrier: R6 single counter per (dir,bg).
#define REC_THREADS 384
#define WS2_STRIDE  772
#define REC_SMEM_FLOATS (36*WS2_STRIDE + 6144 + 576 + 48 + 192 + 1728)

__global__ void __launch_bounds__(REC_THREADS) gru_rec(
    const float* __restrict__ Whf, const float* __restrict__ Whb,
    const float* __restrict__ bhf, const float* __restrict__ bhb)
{
    extern __shared__ float sm[];
    float* Ws2   = sm;                          // 36 x 772 = 27792
    float* Hs    = sm + 36 * WS2_STRIDE;        // 6144: [k][16]
    float* xs    = Hs + 6144;                   // 576: [(g*12+u)*16 + bl]
    float* bh    = xs + 576;                    // 48 (36 used)
    float* Hn    = bh + 48;                     // 192: [ul*16 + bl]
    float* parts = Hn + 192;                    // 1728 = 3 kq x (3 g x 192)

    const int bid = blockIdx.x;
    const int dir = bid >> 6;
    const int bg  = (bid >> 5) & 1;
    const int u0  = (bid & 31) * 12;
    const int b0  = bg * 16;
    const int tid = threadIdx.x;
    const int w    = tid >> 5, lane = tid & 31;
    const int ug   = w % 3;
    const int kq   = w / 3;
    const int uu   = lane >> 3;                 // 0..3
    const int p    = lane & 7;                  // 0..7
    const int ul   = ug * 4 + uu;               // 0..11
    const int k0   = kq * 96;
    const int j    = u0 + ul;
    const int slot = ul * 16 + 2 * p;

    const float* Wh  = dir ? Whb : Whf;
    const float* bhh = dir ? bhb : bhf;
    int* barp = g_bar + (dir * 2 + bg) * SS;

    // stationary pair-duplicated weights: 36 rows x 384 k
    for (int idx = tid; idx < 36 * 384; idx += REC_THREADS) {
        int k = idx % 384;
        int ru = idx / 384;
        int g = ru / 12, u = ru % 12;
        float v = Wh[((size_t)(g * 384 + u0 + u)) * 384 + k];
        Ws2[ru * WS2_STRIDE + 2 * k]     = v;
        Ws2[ru * WS2_STRIDE + 2 * k + 1] = v;
    }
    if (tid < 36) {
        int g = tid / 12, u = tid % 12;
        bh[tid] = bhh[g * 384 + u0 + u];
    }

    const float* wRp = Ws2 + (0 * 12 + ul) * WS2_STRIDE + 2 * k0;
    const float* wZp = Ws2 + (1 * 12 + ul) * WS2_STRIDE + 2 * k0;
    const float* wNp = Ws2 + (2 * 12 + ul) * WS2_STRIDE + 2 * k0;

    // initial xs prefetch (s = 0): 576 entries = 384 + 192
    float xpref[2];
    {
        int t0 = dir ? (SS - 1) : 0;
        {
            int idx = tid;
            int bl = idx & 15, ru = idx >> 4;
            int g = ru / 12, u = ru % 12;
            xpref[0] = __ldcg(&g_XW[((size_t)(dir * G3 + g * 384 + u0 + u)) * M16K + t0 * 32 + b0 + bl]);
        }
        if (tid < 192) {
            int idx = tid + 384;
            int bl = idx & 15, ru = idx >> 4;
            int g = ru / 12, u = ru % 12;
            xpref[1] = __ldcg(&g_XW[((size_t)(dir * G3 + g * 384 + u0 + u)) * M16K + t0 * 32 + b0 + bl]);
        }
    }

    int pp = 0;
    for (int s = 0; s < SS; ++s) {
        const int t = dir ? (SS - 1 - s) : s;

        xs[tid] = xpref[0];
        if (tid < 192) xs[tid + 384] = xpref[1];
        // stage group H (24KB): flat copy, 4 float4 per thread
        {
            const float4* src = (const float4*)(&g_H[dir][bg][pp][0]);
            float4* dst = (float4*)Hs;
#pragma unroll
            for (int i = 0; i < 4; ++i)
                dst[tid + i * REC_THREADS] = __ldcg(src + tid + i * REC_THREADS);
        }
        __syncthreads();

        // prefetch next step's xs (overlaps compute)
        if (s + 1 < SS) {
            int tn = dir ? (SS - 2 - s) : (s + 1);
            {
                int idx = tid;
                int bl = idx & 15, ru = idx >> 4;
                int g = ru / 12, u = ru % 12;
                xpref[0] = __ldcg(&g_XW[((size_t)(dir * G3 + g * 384 + u0 + u)) * M16K + tn * 32 + b0 + bl]);
            }
            if (tid < 192) {
                int idx = tid + 384;
                int bl = idx & 15, ru = idx >> 4;
                int g = ru / 12, u = ru % 12;
                xpref[1] = __ldcg(&g_XW[((size_t)(dir * G3 + g * 384 + u0 + u)) * M16K + tn * 32 + b0 + bl]);
            }
        }

        // quarter-K 3-gate dot, 2 batches per lane (FFMA2)
        unsigned long long aR, aZ, aN;
        if (kq == 0) {
            aR = pk2(bh[ul], bh[ul]);
            aZ = pk2(bh[12 + ul], bh[12 + ul]);
            aN = pk2(bh[24 + ul], bh[24 + ul]);
        } else {
            aR = aZ = aN = pk2(0.f, 0.f);
        }
        const float* hp = Hs + k0 * 16 + 2 * p;
#pragma unroll 4
        for (int kk = 0; kk < 96; kk += 2) {
            unsigned long long h0 = *(const unsigned long long*)(hp + kk * 16);
            unsigned long long h1 = *(const unsigned long long*)(hp + (kk + 1) * 16);
            ulonglong2 wr = *(const ulonglong2*)(wRp + 2 * kk);
            ulonglong2 wz = *(const ulonglong2*)(wZp + 2 * kk);
            ulonglong2 wn = *(const ulonglong2*)(wNp + 2 * kk);
            FMA2(aR, wr.x, h0, aR); FMA2(aR, wr.y, h1, aR);
            FMA2(aZ, wz.x, h0, aZ); FMA2(aZ, wz.y, h1, aZ);
            FMA2(aN, wn.x, h0, aN); FMA2(aN, wn.y, h1, aN);
        }

        if (kq > 0) {
            float* pb = parts + (kq - 1) * 576;
            *(float2*)&pb[slot]       = upk2(aR);
            *(float2*)&pb[192 + slot] = upk2(aZ);
            *(float2*)&pb[384 + slot] = upk2(aN);
        }
        __syncthreads();

        if (kq == 0) {
            float2 fR = upk2(aR), fZ = upk2(aZ), fN = upk2(aN);
#pragma unroll
            for (int q = 0; q < 3; ++q) {
                const float* pb = parts + q * 576;
                float2 r2 = *(const float2*)&pb[slot];
                float2 z2 = *(const float2*)&pb[192 + slot];
                float2 n2 = *(const float2*)&pb[384 + slot];
                fR.x += r2.x; fR.y += r2.y;
                fZ.x += z2.x; fZ.y += z2.y;
                fN.x += n2.x; fN.y += n2.y;
            }
            float2 xr = *(const float2*)&xs[(0 * 12 + ul) * 16 + 2 * p];
            float2 xz = *(const float2*)&xs[(1 * 12 + ul) * 16 + 2 * p];
            float2 xn = *(const float2*)&xs[(2 * 12 + ul) * 16 + 2 * p];
            float2 hold = *(const float2*)&Hs[j * 16 + 2 * p];

            float r0 = 1.f / (1.f + expf(-(xr.x + fR.x)));
            float r1 = 1.f / (1.f + expf(-(xr.y + fR.y)));
            float z0 = 1.f / (1.f + expf(-(xz.x + fZ.x)));
            float z1 = 1.f / (1.f + expf(-(xz.y + fZ.y)));
            float n0 = tanhf(xn.x + r0 * fN.x);
            float n1 = tanhf(xn.y + r1 * fN.y);
            float h0 = n0 + z0 * (hold.x - n0);
            float h1 = n1 + z1 * (hold.y - n1);

            __stcg((float2*)&g_H[dir][bg][pp ^ 1][j * 16 + 2 * p], make_float2(h0, h1));
            Hn[slot]     = h0;
            Hn[slot + 1] = h1;
        }
        __syncthreads();

        if (tid == 0) red_release_add(&barp[s]);

        // OUT write (off critical path): 192 values, [ul][bl] -> [t*32+b0+bl][dir*384+u0+ul]
        if (tid < 192) {
            int b2 = tid / 12, jj = tid - b2 * 12;
            g_OUT[(size_t)(t * 32 + b0 + b2) * (2 * HH) + dir * HH + u0 + jj] = Hn[jj * 16 + b2];
        }

        if (tid == 0) {
            while (ld_acquire(&barp[s]) < 32) { }
        }
        __syncthreads();
        pp ^= 1;
    }
}

// ------------------------- softmax + attention pooling ----------------------
__global__ void __launch_bounds__(128) attn_pool(float* __restrict__ out)
{
    __shared__ float sc[SS];
    __shared__ float red[128];
    const int b = blockIdx.x;
    const int chunk = blockIdx.y;
    const int tid = threadIdx.x;

    for (int t = tid; t < SS; t += 128) sc[t] = g_scores[t * 32 + b];
    __syncthreads();

    float mx = -3.4e38f;
    for (int t = tid; t < SS; t += 128) mx = fmaxf(mx, sc[t]);
    red[tid] = mx;
    __syncthreads();
    for (int sft = 64; sft > 0; sft >>= 1) {
        if (tid < sft) red[tid] = fmaxf(red[tid], red[tid + sft]);
        __syncthreads();
    }
    mx = red[0];
    __syncthreads();

    float lsum = 0.f;
    for (int t = tid; t < SS; t += 128) {
        float e = expf(sc[t] - mx);
        sc[t] = e;
        lsum += e;
    }
    red[tid] = lsum;
    __syncthreads();
    for (int sft = 64; sft > 0; sft >>= 1) {
        if (tid < sft) red[tid] += red[tid + sft];
        __syncthreads();
    }
    float inv = 1.f / red[0];
    __syncthreads();

    if (tid < 96) {
        int dd = chunk * 96 + tid;
        float acc = 0.f;
#pragma unroll 4
        for (int t = 0; t < SS; ++t)
            acc = fmaf(sc[t], g_OUT[(size_t)(t * 32 + b) * (2 * HH) + dd], acc);
        out[b * (2 * HH) + dd] = acc * inv;
    }
}

// --------------------------------- launch -----------------------------------
extern "C" void kernel_launch(void* const* d_in, const int* in_sizes, int n_in,
                              void* d_out, int out_size)
{
    const float* ip   = (const float*)d_in[0];
    const float* Wihf = (const float*)d_in[1];
    const float* Whhf = (const float*)d_in[2];
    const float* bihf = (const float*)d_in[3];
    const float* bhhf = (const float*)d_in[4];
    const float* Wihb = (const float*)d_in[5];
    const float* Whhb = (const float*)d_in[6];
    const float* bihb = (const float*)d_in[7];
    const float* bhhb = (const float*)d_in[8];
    const float* Wa   = (const float*)d_in[9];
    const float* ba   = (const float*)d_in[10];
    const float* ctx  = (const float*)d_in[11];
    float* out = (float*)d_out;

    const __half *pAc, *pBc, *pWac, *pOc;
    cudaGetSymbolAddress((void**)&pAc, g_Ac);
    cudaGetSymbolAddress((void**)&pBc, g_Bc);
    cudaGetSymbolAddress((void**)&pWac, g_Wac);
    cudaGetSymbolAddress((void**)&pOc, g_Oc);

    const int rec_smem = REC_SMEM_FLOATS * 4;   // 146,112 bytes
    cudaFuncSetAttribute(gru_rec, cudaFuncAttributeMaxDynamicSharedMemorySize, rec_smem);
    cudaFuncSetAttribute(hgemm_kernel<0>, cudaFuncAttributeMaxDynamicSharedMemorySize, HG_DYN_SMEM);
    cudaFuncSetAttribute(hgemm_kernel<1>, cudaFuncAttributeMaxDynamicSharedMemorySize, HG_DYN_SMEM);

    init_kernel<<<64, 256>>>();
    {
        int tot = (M16K + NROWS + 2 * HH) * (DD / 4);
        convert_split<<<(tot + 255) / 256, 256>>>(ip, Wihf, Wihb, Wa);
    }
    hgemm_kernel<0><<<dim3(NROWS / 256, M16K / 128), 256, HG_DYN_SMEM>>>(
        pAc, pBc, bihf, bihb);
    gru_rec<<<128, REC_THREADS, rec_smem>>>(Whhf, Whhb, bhhf, bhhb);
    {
        int tot = M16K * (DD / 4);
        out_convert<<<(tot + 255) / 256, 256>>>();
    }
    hgemm_kernel<1><<<dim3((2 * HH) / 256, M16K / 128), 256, HG_DYN_SMEM>>>(
        pWac, pOc, ba, ctx);
    attn_pool<<<dim3(32, 8), 128>>>(out);
}

// round 17
// speedup vs baseline: 1.0054x; 1.0054x over previous
#include <cuda_runtime.h>
#include <cuda_fp16.h>
#include <math.h>
#include <stdint.h>

#define BB   32
#define SS   512
#define DD   768
#define HH   384
#define G3   (3*HH)      // 1152
#define NROWS (2*G3)     // 2304
#define M16K (SS*BB)     // 16384
#define KCP  (2*DD)      // 1536  (A-side 2-term split: [hi|lo])

// ---------------- scratch (static device globals; no runtime alloc) ----------
__device__ float g_XW[(size_t)NROWS * M16K];        // [n][m], m = t*32+b
__device__ float g_OUT[(size_t)M16K * (2*HH)];      // [m][768]
__device__ float g_H[2][2][HH * BB];                // [dir][buf][k*32+b]
__device__ int   g_bar[2 * SS];                     // per-step arrival counters
__device__ float g_scores[M16K];
// fp16 operands: A carries [hi|lo] (K=1536); B carries single hi segment (K=768)
__device__ __half g_Ac [(size_t)NROWS * KCP];       // proj A: [Wh|Wl]
__device__ __half g_Bc [(size_t)M16K  * DD];        // proj B: Xh
__device__ __half g_Wac[(size_t)(2*HH) * KCP];      // attn A: [Wah|Wal]
__device__ __half g_Oc [(size_t)M16K  * DD];        // attn B: Oh

// ============================ PTX helpers ====================================
__device__ __forceinline__ uint32_t smem_u32(const void* p) {
    uint32_t a;
    asm("{ .reg .u64 t; cvta.to.shared.u64 t, %1; cvt.u32.u64 %0, t; }"
        : "=r"(a) : "l"(p));
    return a;
}

#define CP_ASYNC16(saddr, gptr) \
    asm volatile("cp.async.cg.shared.global [%0], [%1], 16;" \
                 :: "r"(saddr), "l"(gptr) : "memory")
#define CP_COMMIT() asm volatile("cp.async.commit_group;" ::: "memory")
#define CP_WAIT2()  asm volatile("cp.async.wait_group 2;" ::: "memory")

#define LDMATRIX_X4(r0, r1, r2, r3, addr) \
    asm volatile("ldmatrix.sync.aligned.m8n8.x4.shared.b16 {%0,%1,%2,%3}, [%4];" \
                 : "=r"(r0), "=r"(r1), "=r"(r2), "=r"(r3) : "r"(addr))

#define MMA16816(c0, c1, c2, c3, a0, a1, a2, a3, b0, b1) \
    asm volatile("mma.sync.aligned.m16n8k16.row.col.f32.f16.f16.f32 " \
                 "{%0,%1,%2,%3}, {%4,%5,%6,%7}, {%8,%9}, {%0,%1,%2,%3};" \
                 : "+f"(c0), "+f"(c1), "+f"(c2), "+f"(c3) \
                 : "r"(a0), "r"(a1), "r"(a2), "r"(a3), "r"(b0), "r"(b1))

__device__ __forceinline__ void red_release_add(int* p) {
    asm volatile("red.release.gpu.global.add.u32 [%0], 1;" :: "l"(p) : "memory");
}
__device__ __forceinline__ int ld_acquire(const int* p) {
    int v;
    asm volatile("ld.acquire.gpu.global.u32 %0, [%1];" : "=r"(v) : "l"(p) : "memory");
    return v;
}

// packed fp32x2
__device__ __forceinline__ unsigned long long pk2(float a, float b) {
    unsigned long long r;
    asm("mov.b64 %0, {%1, %2};" : "=l"(r) : "f"(a), "f"(b));
    return r;
}
__device__ __forceinline__ float2 upk2(unsigned long long v) {
    float2 f;
    asm("mov.b64 {%0, %1}, %2;" : "=f"(f.x), "=f"(f.y) : "l"(v));
    return f;
}
#define FMA2(d, a, b, c) \
    asm("fma.rn.f32x2 %0, %1, %2, %3;" : "=l"(d) : "l"(a), "l"(b), "l"(c))

// ---------------------------------- init ------------------------------------
__global__ void init_kernel() {
    int idx = blockIdx.x * blockDim.x + threadIdx.x;
    int nthr = gridDim.x * blockDim.x;
    float* h = &g_H[0][0][0];
    for (int i = idx; i < 2 * 2 * HH * BB; i += nthr) h[i] = 0.f;
    for (int i = idx; i < 2 * SS; i += nthr) g_bar[i] = 0;
    for (int i = idx; i < M16K; i += nthr) g_scores[i] = 0.f;
}

// ---------------- fp32 -> fp16 hi/lo split conversion ------------------------
// X rows -> g_Bc (hi only, K=768); Wcat -> g_Ac [Wh|Wl]; Wa -> g_Wac [Wah|Wal].
__global__ void __launch_bounds__(256) convert_split(
    const float* __restrict__ ip,
    const float* __restrict__ Wf, const float* __restrict__ Wb,
    const float* __restrict__ Wa)
{
    const int TOT = (M16K + NROWS + 2 * HH) * (DD / 4);
    int idx = blockIdx.x * blockDim.x + threadIdx.x;
    if (idx >= TOT) return;
    int row = idx / (DD / 4);
    int k = (idx - row * (DD / 4)) * 4;

    const float* src;
    if (row < M16K) {
        int b = row & 31, t = row >> 5;
        src = ip + ((size_t)(b * SS + t)) * DD + k;
    } else if (row < M16K + NROWS) {
        int n = row - M16K;
        src = ((n < G3) ? (Wf + (size_t)n * DD) : (Wb + (size_t)(n - G3) * DD)) + k;
    } else {
        int n = row - M16K - NROWS;
        src = Wa + (size_t)n * (2 * HH) + k;
    }
    float4 v = *(const float4*)src;
    union { __half h[4]; uint2 u; } hi, lo;
    hi.h[0] = __float2half_rn(v.x); lo.h[0] = __float2half_rn(v.x - __half2float(hi.h[0]));
    hi.h[1] = __float2half_rn(v.y); lo.h[1] = __float2half_rn(v.y - __half2float(hi.h[1]));
    hi.h[2] = __float2half_rn(v.z); lo.h[2] = __float2half_rn(v.z - __half2float(hi.h[2]));
    hi.h[3] = __float2half_rn(v.w); lo.h[3] = __float2half_rn(v.w - __half2float(hi.h[3]));

    if (row < M16K) {                        // X: hi only
        __half* dst = g_Bc + (size_t)row * DD;
        *(uint2*)(dst + k)      = hi.u;
    } else if (row < M16K + NROWS) {         // Wcat: [h | l]
        __half* dst = g_Ac + (size_t)(row - M16K) * KCP;
        *(uint2*)(dst + k)      = hi.u;
        *(uint2*)(dst + DD + k) = lo.u;
    } else {                                 // Wa: [h | l]
        __half* dst = g_Wac + (size_t)(row - M16K - NROWS) * KCP;
        *(uint2*)(dst + k)      = hi.u;
        *(uint2*)(dst + DD + k) = lo.u;
    }
}

// -------------------- OUT fp32 -> fp16 hi (for attn HGEMM) ------------------
__global__ void __launch_bounds__(256) out_convert() {
    int idx = blockIdx.x * blockDim.x + threadIdx.x;
    if (idx >= M16K * (DD / 4)) return;
    int m = idx / (DD / 4);
    int k = (idx - m * (DD / 4)) * 4;
    float4 v = *(const float4*)&g_OUT[(size_t)m * (2 * HH) + k];
    union { __half h[4]; uint2 u; } hi;
    hi.h[0] = __float2half_rn(v.x);
    hi.h[1] = __float2half_rn(v.y);
    hi.h[2] = __float2half_rn(v.z);
    hi.h[3] = __float2half_rn(v.w);
    *(uint2*)(g_Oc + (size_t)m * DD + k) = hi.u;
}

// ----------------------- shared HGEMM (mma.sync, B-reuse) --------------------
// C[n 256][m 128] = Ah[n][768]*B^T + Al[n][768]*B^T (same B fragments reused).
// 8 warps = 4(n) x 2(m), warp tile 64x64. 4-stage cp.async, K-loop = 24 chunks.
#define HG_ASEG 20480                   // one A segment: 256 rows * 80B
#define HG_A_ST (2 * HG_ASEG)           // hi + lo
#define HG_B_ST 10240                   // 128 rows * 80B
#define HG_DYN_SMEM (4 * (HG_A_ST + HG_B_ST))   // 204800

template <int MODE>
__global__ void __launch_bounds__(256, 1) hgemm_kernel(
    const __half* __restrict__ Ag, const __half* __restrict__ Bg,
    const float* __restrict__ e0, const float* __restrict__ e1)
{
    extern __shared__ char dyn[];
    const uint32_t Abase = smem_u32(dyn);
    const uint32_t Bbase = Abase + 4 * HG_A_ST;

    const int tid  = threadIdx.x;
    const int wid  = tid >> 5, lane = tid & 31;
    const int wn   = wid >> 1;            // 0..3
    const int wm   = wid & 1;             // 0..1
    const int n0   = blockIdx.x * 256;
    const int m0   = blockIdx.y * 128;

    const int KT = DD / 32;               // 24

    auto load_stage = [&](int buf, int kt) {
        uint32_t as = Abase + buf * HG_A_ST;
        uint32_t bs = Bbase + buf * HG_B_ST;
#pragma unroll
        for (int i = 0; i < 4; ++i) {                    // A hi + lo
            int idx = tid + i * 256;
            int row = idx >> 2, c = idx & 3;
            const __half* ga = Ag + (size_t)(n0 + row) * KCP + kt * 32 + c * 8;
            CP_ASYNC16(as + row * 80 + c * 16, ga);
            CP_ASYNC16(as + HG_ASEG + row * 80 + c * 16, ga + DD);
        }
#pragma unroll
        for (int i = 0; i < 2; ++i) {                    // B (single segment)
            int idx = tid + i * 256;
            int row = idx >> 2, c = idx & 3;
            const __half* gb = Bg + (size_t)(m0 + row) * DD + kt * 32 + c * 8;
            CP_ASYNC16(bs + row * 80 + c * 16, gb);
        }
        CP_COMMIT();
    };

    float acc[4][8][4];
#pragma unroll
    for (int i = 0; i < 4; i++)
#pragma unroll
        for (int j = 0; j < 8; j++)
#pragma unroll
            for (int r = 0; r < 4; r++) acc[i][j][r] = 0.f;

    load_stage(0, 0);
    load_stage(1, 1);
    load_stage(2, 2);

    const int lr = lane & 15;
    const int lc = lane >> 4;

    for (int kt = 0; kt < KT; ++kt) {
        CP_WAIT2();
        __syncthreads();
        if (kt + 3 < KT) load_stage((kt + 3) & 3, kt + 3);
        else CP_COMMIT();

        uint32_t as = Abase + (kt & 3) * HG_A_ST;
        uint32_t bs = Bbase + (kt & 3) * HG_B_ST;

#pragma unroll
        for (int kk = 0; kk < 2; ++kk) {
            uint32_t bfr[8][2];
#pragma unroll
            for (int bm = 0; bm < 4; ++bm) {
                uint32_t r0, r1, r2, r3;
                uint32_t addr = bs + (wm * 64 + bm * 16 + lr) * 80 + (kk * 2 + lc) * 16;
                LDMATRIX_X4(r0, r1, r2, r3, addr);
                bfr[bm * 2 + 0][0] = r0; bfr[bm * 2 + 0][1] = r2;
                bfr[bm * 2 + 1][0] = r1; bfr[bm * 2 + 1][1] = r3;
            }
#pragma unroll
            for (int seg = 0; seg < 2; ++seg) {
                uint32_t asg = as + seg * HG_ASEG;
#pragma unroll
                for (int fn = 0; fn < 4; ++fn) {
                    uint32_t a0, a1, a2, a3;
                    uint32_t addr = asg + (wn * 64 + fn * 16 + lr) * 80 + (kk * 2 + lc) * 16;
                    LDMATRIX_X4(a0, a1, a2, a3, addr);
#pragma unroll
                    for (int fm = 0; fm < 8; ++fm) {
                        MMA16816(acc[fn][fm][0], acc[fn][fm][1], acc[fn][fm][2], acc[fn][fm][3],
                                 a0, a1, a2, a3, bfr[fm][0], bfr[fm][1]);
                    }
                }
            }
        }
    }

    const int crow = lane >> 2;
    const int ccol = 2 * (lane & 3);

    if (MODE == 0) {
        // ---- proj epilogue: bias + direct quad-coalesced float2 stores ----
#pragma unroll
        for (int fn = 0; fn < 4; ++fn) {
#pragma unroll
            for (int fm = 0; fm < 8; ++fm) {
                int n = n0 + wn * 64 + fn * 16 + crow;
                int n2 = n + 8;
                int c = m0 + wm * 64 + fm * 8 + ccol;
                float bv1 = (n  < G3) ? __ldg(e0 + n)  : __ldg(e1 + n  - G3);
                float bv2 = (n2 < G3) ? __ldg(e0 + n2) : __ldg(e1 + n2 - G3);
                float2 v1 = make_float2(acc[fn][fm][0] + bv1, acc[fn][fm][1] + bv1);
                float2 v2 = make_float2(acc[fn][fm][2] + bv2, acc[fn][fm][3] + bv2);
                *(float2*)&g_XW[(size_t)n  * M16K + c] = v1;
                *(float2*)&g_XW[(size_t)n2 * M16K + c] = v2;
            }
        }
    } else {
        // ---- attn epilogue: tanh(acc + ba[n]) * ctx[n], reduce over n ----
        __syncthreads();
        float* Msum = (float*)dyn;          // [128]
        if (tid < 128) Msum[tid] = 0.f;
        __syncthreads();
#pragma unroll
        for (int fm = 0; fm < 8; ++fm) {
            int c = wm * 64 + fm * 8 + ccol;
            float s0 = 0.f, s1 = 0.f;
#pragma unroll
            for (int fn = 0; fn < 4; ++fn) {
                int na = n0 + wn * 64 + fn * 16 + crow;
                int nb = na + 8;
                float ba_a = __ldg(e0 + na), ba_b = __ldg(e0 + nb);
                float cx_a = __ldg(e1 + na), cx_b = __ldg(e1 + nb);
                s0 += tanhf(acc[fn][fm][0] + ba_a) * cx_a
                    + tanhf(acc[fn][fm][2] + ba_b) * cx_b;
                s1 += tanhf(acc[fn][fm][1] + ba_a) * cx_a
                    + tanhf(acc[fn][fm][3] + ba_b) * cx_b;
            }
            atomicAdd(&Msum[c], s0);
            atomicAdd(&Msum[c + 1], s1);
        }
        __syncthreads();
        if (tid < 128) atomicAdd(&g_scores[m0 + tid], Msum[tid]);
    }
}

// ---------------------------- GRU recurrence (FFMA2) -------------------------
// EXACT R6/R15 structure (best known): frozen.
#define REC_THREADS 384
#define WS2_STRIDE  772
#define REC_SMEM_FLOATS (18*WS2_STRIDE + 12288 + 576 + 32 + 192 + 1728)

__global__ void __launch_bounds__(REC_THREADS) gru_rec(
    const float* __restrict__ Whf, const float* __restrict__ Whb,
    const float* __restrict__ bhf, const float* __restrict__ bhb)
{
    extern __shared__ float sm[];
    float* Ws2   = sm;
    float* Hs    = sm + 18 * WS2_STRIDE;
    float* xs    = Hs + 12288;
    float* bh    = xs + 576;
    float* Hn    = bh + 32;
    float* parts = Hn + 192;

    const int bid = blockIdx.x;
    const int dir = bid >> 6;
    const int u0  = (bid & 63) * 6;
    const int tid = threadIdx.x;
    const int w    = tid >> 5, lane = tid & 31;
    const int ug   = w % 3;
    const int kq   = w / 3;
    const int uu   = lane >> 4;
    const int p    = lane & 15;
    const int ul   = 2 * ug + uu;
    const int k0   = kq * 96;
    const int j    = u0 + ul;
    const int slot = ul * 32 + 2 * p;

    const float* Wh  = dir ? Whb : Whf;
    const float* bhh = dir ? bhb : bhf;

    for (int idx = tid; idx < 18 * 384; idx += REC_THREADS) {
        int k = idx % 384;
        int ru = idx / 384;
        int g = ru / 6, u = ru % 6;
        float v = Wh[((size_t)(g * 384 + u0 + u)) * 384 + k];
        Ws2[ru * WS2_STRIDE + 2 * k]     = v;
        Ws2[ru * WS2_STRIDE + 2 * k + 1] = v;
    }
    if (tid < 18) {
        int g = tid / 6, u = tid % 6;
        bh[tid] = bhh[g * 384 + u0 + u];
    }

    const float* wRp = Ws2 + (0 * 6 + ul) * WS2_STRIDE + 2 * k0;
    const float* wZp = Ws2 + (1 * 6 + ul) * WS2_STRIDE + 2 * k0;
    const float* wNp = Ws2 + (2 * 6 + ul) * WS2_STRIDE + 2 * k0;

    float xpref[2];
    {
        int t0 = dir ? (SS - 1) : 0;
        {
            int idx = tid;
            int b = idx & 31, ru = idx >> 5;
            int g = ru / 6, u = ru % 6;
            xpref[0] = __ldcg(&g_XW[((size_t)(dir * G3 + g * 384 + u0 + u)) * M16K + t0 * 32 + b]);
        }
        if (tid < 192) {
            int idx = tid + 384;
            int b = idx & 31, ru = idx >> 5;
            int g = ru / 6, u = ru % 6;
            xpref[1] = __ldcg(&g_XW[((size_t)(dir * G3 + g * 384 + u0 + u)) * M16K + t0 * 32 + b]);
        }
    }

    int pp = 0;
    for (int s = 0; s < SS; ++s) {
        const int t = dir ? (SS - 1 - s) : s;

        xs[tid] = xpref[0];
        if (tid < 192) xs[tid + 384] = xpref[1];
        {
            const float4* src = (const float4*)(&g_H[dir][pp][0]);
            float4* dst = (float4*)Hs;
#pragma unroll
            for (int i = 0; i < 8; ++i)
                dst[tid + i * REC_THREADS] = __ldcg(src + tid + i * REC_THREADS);
        }
        __syncthreads();

        if (s + 1 < SS) {
            int tn = dir ? (SS - 2 - s) : (s + 1);
            {
                int idx = tid;
                int b = idx & 31, ru = idx >> 5;
                int g = ru / 6, u = ru % 6;
                xpref[0] = __ldcg(&g_XW[((size_t)(dir * G3 + g * 384 + u0 + u)) * M16K + tn * 32 + b]);
            }
            if (tid < 192) {
                int idx = tid + 384;
                int b = idx & 31, ru = idx >> 5;
                int g = ru / 6, u = ru % 6;
                xpref[1] = __ldcg(&g_XW[((size_t)(dir * G3 + g * 384 + u0 + u)) * M16K + tn * 32 + b]);
            }
        }

        unsigned long long aR, aZ, aN;
        if (kq == 0) {
            aR = pk2(bh[ul], bh[ul]);
            aZ = pk2(bh[6 + ul], bh[6 + ul]);
            aN = pk2(bh[12 + ul], bh[12 + ul]);
        } else {
            aR = aZ = aN = pk2(0.f, 0.f);
        }
        const float* hp = Hs + k0 * 32 + 2 * p;
#pragma unroll 4
        for (int kk = 0; kk < 96; kk += 2) {
            unsigned long long h0 = *(const unsigned long long*)(hp + kk * 32);
            unsigned long long h1 = *(const unsigned long long*)(hp + (kk + 1) * 32);
            ulonglong2 wr = *(const ulonglong2*)(wRp + 2 * kk);
            ulonglong2 wz = *(const ulonglong2*)(wZp + 2 * kk);
            ulonglong2 wn = *(const ulonglong2*)(wNp + 2 * kk);
            FMA2(aR, wr.x, h0, aR); FMA2(aR, wr.y, h1, aR);
            FMA2(aZ, wz.x, h0, aZ); FMA2(aZ, wz.y, h1, aZ);
            FMA2(aN, wn.x, h0, aN); FMA2(aN, wn.y, h1, aN);
        }

        if (kq > 0) {
            float* pb = parts + (kq - 1) * 576;
            *(float2*)&pb[slot]       = upk2(aR);
            *(float2*)&pb[192 + slot] = upk2(aZ);
            *(float2*)&pb[384 + slot] = upk2(aN);
        }
        __syncthreads();

        if (kq == 0) {
            float2 fR = upk2(aR), fZ = upk2(aZ), fN = upk2(aN);
#pragma unroll
            for (int q = 0; q < 3; ++q) {
                const float* pb = parts + q * 576;
                float2 r2 = *(const float2*)&pb[slot];
                float2 z2 = *(const float2*)&pb[192 + slot];
                float2 n2 = *(const float2*)&pb[384 + slot];
                fR.x += r2.x; fR.y += r2.y;
                fZ.x += z2.x; fZ.y += z2.y;
                fN.x += n2.x; fN.y += n2.y;
            }
            float2 xr = *(const float2*)&xs[(0 * 6 + ul) * 32 + 2 * p];
            float2 xz = *(const float2*)&xs[(1 * 6 + ul) * 32 + 2 * p];
            float2 xn = *(const float2*)&xs[(2 * 6 + ul) * 32 + 2 * p];
            float2 hold = *(const float2*)&Hs[j * 32 + 2 * p];

            float r0 = 1.f / (1.f + expf(-(xr.x + fR.x)));
            float r1 = 1.f / (1.f + expf(-(xr.y + fR.y)));
            float z0 = 1.f / (1.f + expf(-(xz.x + fZ.x)));
            float z1 = 1.f / (1.f + expf(-(xz.y + fZ.y)));
            float n0 = tanhf(xn.x + r0 * fN.x);
            float n1 = tanhf(xn.y + r1 * fN.y);
            float h0 = n0 + z0 * (hold.x - n0);
            float h1 = n1 + z1 * (hold.y - n1);

            __stcg((float2*)&g_H[dir][pp ^ 1][j * 32 + 2 * p], make_float2(h0, h1));
            Hn[slot]     = h0;
            Hn[slot + 1] = h1;
        }
        __syncthreads();

        if (tid == 0) red_release_add(&g_bar[dir * SS + s]);

        if (tid < 192) {
            int b2 = tid / 6, jj = tid - b2 * 6;
            g_OUT[(size_t)(t * 32 + b2) * (2 * HH) + dir * HH + u0 + jj] = Hn[jj * 32 + b2];
        }

        if (tid == 0) {
            while (ld_acquire(&g_bar[dir * SS + s]) < 64) { }
        }
        __syncthreads();
        pp ^= 1;
    }
}

// ------------------------- softmax + attention pooling ----------------------
// grid (32, 8): b = blockIdx.x, chunk = blockIdx.y (96 dims each). 128 threads.
__global__ void __launch_bounds__(128) attn_pool(float* __restrict__ out)
{
    __shared__ float sc[SS];
    __shared__ float red[128];
    const int b = blockIdx.x;
    const int chunk = blockIdx.y;
    const int tid = threadIdx.x;

    for (int t = tid; t < SS; t += 128) sc[t] = g_scores[t * 32 + b];
    __syncthreads();

    float mx = -3.4e38f;
    for (int t = tid; t < SS; t += 128) mx = fmaxf(mx, sc[t]);
    red[tid] = mx;
    __syncthreads();
    for (int sft = 64; sft > 0; sft >>= 1) {
        if (tid < sft) red[tid] = fmaxf(red[tid], red[tid + sft]);
        __syncthreads();
    }
    mx = red[0];
    __syncthreads();

    float lsum = 0.f;
    for (int t = tid; t < SS; t += 128) {
        float e = expf(sc[t] - mx);
        sc[t] = e;
        lsum += e;
    }
    red[tid] = lsum;
    __syncthreads();
    for (int sft = 64; sft > 0; sft >>= 1) {
        if (tid < sft) red[tid] += red[tid + sft];
        __syncthreads();
    }
    float inv = 1.f / red[0];
    __syncthreads();

    if (tid < 96) {
        int dd = chunk * 96 + tid;
        float acc = 0.f;
#pragma unroll 4
        for (int t = 0; t < SS; ++t)
            acc = fmaf(sc[t], g_OUT[(size_t)(t * 32 + b) * (2 * HH) + dd], acc);
        out[b * (2 * HH) + dd] = acc * inv;
    }
}

// --------------------------------- launch -----------------------------------
extern "C" void kernel_launch(void* const* d_in, const int* in_sizes, int n_in,
                              void* d_out, int out_size)
{
    const float* ip   = (const float*)d_in[0];
    const float* Wihf = (const float*)d_in[1];
    const float* Whhf = (const float*)d_in[2];
    const float* bihf = (const float*)d_in[3];
    const float* bhhf = (const float*)d_in[4];
    const float* Wihb = (const float*)d_in[5];
    const float* Whhb = (const float*)d_in[6];
    const float* bihb = (const float*)d_in[7];
    const float* bhhb = (const float*)d_in[8];
    const float* Wa   = (const float*)d_in[9];
    const float* ba   = (const float*)d_in[10];
    const float* ctx  = (const float*)d_in[11];
    float* out = (float*)d_out;

    const __half *pAc, *pBc, *pWac, *pOc;
    cudaGetSymbolAddress((void**)&pAc, g_Ac);
    cudaGetSymbolAddress((void**)&pBc, g_Bc);
    cudaGetSymbolAddress((void**)&pWac, g_Wac);
    cudaGetSymbolAddress((void**)&pOc, g_Oc);

    const int rec_smem = REC_SMEM_FLOATS * 4;   // 114,664 bytes
    cudaFuncSetAttribute(gru_rec, cudaFuncAttributeMaxDynamicSharedMemorySize, rec_smem);
    cudaFuncSetAttribute(hgemm_kernel<0>, cudaFuncAttributeMaxDynamicSharedMemorySize, HG_DYN_SMEM);
    cudaFuncSetAttribute(hgemm_kernel<1>, cudaFuncAttributeMaxDynamicSharedMemorySize, HG_DYN_SMEM);

    init_kernel<<<64, 256>>>();
    {
        int tot = (M16K + NROWS + 2 * HH) * (DD / 4);
        convert_split<<<(tot + 255) / 256, 256>>>(ip, Wihf, Wihb, Wa);
    }
    hgemm_kernel<0><<<dim3(NROWS / 256, M16K / 128), 256, HG_DYN_SMEM>>>(
        pAc, pBc, bihf, bihb);
    gru_rec<<<128, REC_THREADS, rec_smem>>>(Whhf, Whhb, bhhf, bhhb);
    {
        int tot = M16K * (DD / 4);
        out_convert<<<(tot + 255) / 256, 256>>>();
    }
    hgemm_kernel<1><<<dim3((2 * HH) / 256, M16K / 128), 256, HG_DYN_SMEM>>>(
        pWac, pOc, ba, ctx);
    attn_pool<<<dim3(32, 8), 128>>>(out);
}